// round 7
// baseline (speedup 1.0000x reference)
#include <cuda_runtime.h>
#include <cuda_bf16.h>

typedef unsigned int       u32;
typedef unsigned long long u64;

#define D       32
#define KNN     4
#define KAUG    192        // 6 blocks of 32 (3-way bf16 split cross terms)
#define MTILE   128        // samples per CTA
#define NTILE   128        // centers per staged tile
#define KSTEPS  12         // 192 / 16
#define SWR     100        // smem row stride in 32-bit words (200 bf16, conflict-free)
#define ROWB    400        // smem row stride in bytes

// ---------------- smem layout (bytes) ----------------
#define OFF_A    0
#define SZ_AB    (MTILE * ROWB)            // 51200
#define OFF_B    (OFF_A + SZ_AB)           // two buffers
#define OFF_CN   (OFF_B + 2 * SZ_AB)       // 153600: 2048 floats
#define OFF_X    (OFF_CN + 8192)           // 161792: 128*33 floats
#define OFF_CD   (OFF_X + 16896)           // 178688: 128*16 floats
#define OFF_CI   (OFF_CD + 8192)           // 186880: 128*16 ints
#define OFF_IDX  (OFF_CI + 8192)           // 195072: 128*4 ints
#define DYN_SMEM (OFF_IDX + 2048)          // 197120

// ---------------- device scratch ----------------
__device__ __nv_bfloat16 g_a_aug[16384ull * KAUG];
__device__ __nv_bfloat16 g_b_aug[2048ull * KAUG];
__device__ float g_cn[2048];

// ---------------- helpers ----------------
__device__ __forceinline__ u32 smem_u32(const void* p) {
    u32 a;
    asm("{ .reg .u64 t; cvta.to.shared.u64 t, %1; cvt.u32.u64 %0, t; }" : "=r"(a) : "l"(p));
    return a;
}
#define CP16(dst, src) asm volatile("cp.async.cg.shared.global [%0], [%1], 16;" :: "r"(dst), "l"(src))
#define CP4(dst, src)  asm volatile("cp.async.ca.shared.global [%0], [%1], 4;"  :: "r"(dst), "l"(src))
#define CP_COMMIT()    asm volatile("cp.async.commit_group;")
#define CP_WAIT1()     asm volatile("cp.async.wait_group 1;" ::: "memory")
#define CP_WAIT0()     asm volatile("cp.async.wait_group 0;" ::: "memory")

__device__ __forceinline__ void mma_bf16(float& d0, float& d1, float& d2, float& d3,
                                         u32 a0, u32 a1, u32 a2, u32 a3,
                                         u32 b0, u32 b1) {
    asm volatile(
        "mma.sync.aligned.m16n8k16.row.col.f32.bf16.bf16.f32 "
        "{%0,%1,%2,%3}, {%4,%5,%6,%7}, {%8,%9}, {%0,%1,%2,%3};"
        : "+f"(d0), "+f"(d1), "+f"(d2), "+f"(d3)
        : "r"(a0), "r"(a1), "r"(a2), "r"(a3), "r"(b0), "r"(b1));
}

// stable top-4 (strict <, ties keep earlier index; inserts are in increasing f)
struct Top4 {
    float d0, d1, d2, d3;
    int   i0, i1, i2, i3;
    __device__ __forceinline__ void init() {
        d0 = d1 = d2 = d3 = 3.4e38f; i0 = i1 = i2 = i3 = 0;
    }
    __device__ __forceinline__ void insert(float sc, int f) {
        if (sc < d3) {
            bool g0 = sc < d0, g1 = sc < d1, g2 = sc < d2;
            float n3 = g2 ? d2 : sc;             int j3 = g2 ? i2 : f;
            float n2 = g2 ? (g1 ? d1 : sc) : d2; int j2 = g2 ? (g1 ? i1 : f) : i2;
            float n1 = g1 ? (g0 ? d0 : sc) : d1; int j1 = g1 ? (g0 ? i0 : f) : i1;
            d0 = g0 ? sc : d0;                   i0 = g0 ? f : i0;
            d1 = n1; i1 = j1; d2 = n2; i2 = j2; d3 = n3; i3 = j3;
        }
    }
};

// ---------------- prep: 3-way bf16 splits + cnorm ----------------
// A blocks: [u0,u1,u0,u1,u0,u2]; B blocks: [c0,c0,c1,c1,c2,c0]
// sum of products = u0c0+u1c0+u0c1+u1c1+u0c2+u2c0 ~= u.c (err ~2^-27 |u||c|)
__global__ void prep_a_kernel(const float* __restrict__ x, int n) {
    int i = blockIdx.x * blockDim.x + threadIdx.x;
    if (i >= n) return;
    int row = i >> 5, d = i & 31;
    float u = -2.0f * x[i];
    __nv_bfloat16 u0 = __float2bfloat16(u);
    float r1 = u - __bfloat162float(u0);
    __nv_bfloat16 u1 = __float2bfloat16(r1);
    float r2 = r1 - __bfloat162float(u1);
    __nv_bfloat16 u2 = __float2bfloat16(r2);
    __nv_bfloat16* a = g_a_aug + (size_t)row * KAUG;
    a[d] = u0; a[32 + d] = u1; a[64 + d] = u0;
    a[96 + d] = u1; a[128 + d] = u0; a[160 + d] = u2;
}

__global__ void prep_b_kernel(const float* __restrict__ ctrs, int n_fcns) {
    int f = blockIdx.x * blockDim.x + threadIdx.x;
    if (f >= n_fcns) return;
    float cn = 0.0f;
    __nv_bfloat16* b = g_b_aug + (size_t)f * KAUG;
    for (int d = 0; d < D; d++) {
        float c = ctrs[(size_t)f * D + d];
        cn += c * c;
        __nv_bfloat16 c0 = __float2bfloat16(c);
        float r1 = c - __bfloat162float(c0);
        __nv_bfloat16 c1 = __float2bfloat16(r1);
        float r2 = r1 - __bfloat162float(c1);
        __nv_bfloat16 c2 = __float2bfloat16(r2);
        b[d] = c0; b[32 + d] = c0; b[64 + d] = c1;
        b[96 + d] = c1; b[128 + d] = c2; b[160 + d] = c0;
    }
    g_cn[f] = cn;
}

// ---------------- main fused kernel ----------------
// 1 CTA = 128 samples x all centers, 256 threads (8 warps).
// Warp w owns M-rows [16w, 16w+16). A fragments (16x192) live in 48 regs.
// B streams via cp.async double-buffered 128-center tiles; per 8-center
// subtile: 12x mma.sync.m16n8k16 + fused fp32 top-4 epilogue. Then phase B.
__global__ __launch_bounds__(256, 1)
void pwl_gemm_kernel(const float* __restrict__ x,
                     const float* __restrict__ ctrs,
                     const float* __restrict__ wts,
                     const float* __restrict__ offs,
                     float* __restrict__ y,
                     int n_fcns)
{
    extern __shared__ __align__(16) char smem[];
    const int tid  = threadIdx.x;
    const int lane = tid & 31;
    const int w    = tid >> 5;
    const int q    = lane & 3;        // k-quad within fragment
    const int rl   = lane >> 2;       // row/col-lane within fragment
    const int m0   = blockIdx.x * MTILE;
    const int NT   = n_fcns / NTILE;  // 16

    const u32 sb   = smem_u32(smem);
    float* s_cn  = (float*)(smem + OFF_CN);
    float* s_x   = (float*)(smem + OFF_X);    // [128][33]
    float* s_cd  = (float*)(smem + OFF_CD);   // [128][16]
    int*   s_ci  = (int*)  (smem + OFF_CI);   // [128][16]
    int*   s_idx = (int*)  (smem + OFF_IDX);  // [128][4]

    // stage a 128-row x 192-col bf16 tile into padded smem (row stride 400B)
    auto stage_tile = [&](const __nv_bfloat16* g, int row0, u32 dst) {
#pragma unroll
        for (int kk = 0; kk < 12; kk++) {
            int e = tid + kk * 256;          // 0..3071 16B-chunks
            int r = e / 24, c = e % 24;
            CP16(dst + (u32)(r * ROWB + c * 16),
                 (const char*)(g + (size_t)(row0 + r) * KAUG) + c * 16);
        }
    };

    // group 0: A tile + cnorms + B tile 0 ; group 1: B tile 1
    stage_tile(g_a_aug, m0, sb + OFF_A);
#pragma unroll
    for (int i = 0; i < 8; i++)
        CP4(sb + OFF_CN + (tid + i * 256) * 4, (const char*)(g_cn + tid + i * 256));
    stage_tile(g_b_aug, 0, sb + OFF_B);
    CP_COMMIT();
    stage_tile(g_b_aug, NTILE, sb + OFF_B + SZ_AB);
    CP_COMMIT();

    // stage raw x for phase B (plain LDG->STS, overlaps with cp.async)
    for (int i = tid; i < MTILE * D; i += 256) {
        int r = i >> 5, d = i & 31;
        s_x[r * 33 + d] = __ldg(x + (size_t)(m0 + r) * D + d);
    }

    CP_WAIT1();              // group 0 (A + cn + B0) resident
    __syncthreads();

    // ---- load this warp's A fragments into registers (once) ----
    u32 af[KSTEPS][4];
    {
        const u32* aw = (const u32*)(smem + OFF_A);
        const int r0 = 16 * w + rl;
#pragma unroll
        for (int s = 0; s < KSTEPS; s++) {
            int base = r0 * SWR + s * 8 + q;
            af[s][0] = aw[base];
            af[s][1] = aw[base + 8 * SWR];
            af[s][2] = aw[base + 4];
            af[s][3] = aw[base + 8 * SWR + 4];
        }
    }

    Top4 tA, tB;             // rows r0 and r0+8
    tA.init(); tB.init();

    for (int t = 0; t < NT; t++) {
        if (t > 0) { if (t == NT - 1) CP_WAIT0(); else CP_WAIT1(); __syncthreads(); }

        const u32* bw = (const u32*)(smem + OFF_B + (t & 1) * SZ_AB);
        const float* cnb = s_cn + t * NTILE;

        for (int j = 0; j < 16; j++) {
            float d0 = 0.f, d1 = 0.f, d2 = 0.f, d3 = 0.f;
            const u32* bj = bw + (j * 8 + rl) * SWR + q;
#pragma unroll
            for (int s = 0; s < KSTEPS; s++)
                mma_bf16(d0, d1, d2, d3,
                         af[s][0], af[s][1], af[s][2], af[s][3],
                         bj[s * 8], bj[s * 8 + 4]);

            const int colb = j * 8 + q * 2;
            float2 cn2 = *(const float2*)(cnb + colb);
            const int g = t * NTILE + colb;
            tA.insert(d0 + cn2.x, g);
            tA.insert(d1 + cn2.y, g + 1);
            tB.insert(d2 + cn2.x, g);
            tB.insert(d3 + cn2.y, g + 1);
        }

        __syncthreads();     // all warps done reading this B buffer
        if (t + 2 < NT) {
            stage_tile(g_b_aug, (t + 2) * NTILE, sb + OFF_B + (t & 1) * SZ_AB);
            CP_COMMIT();
        }
    }

    // ---- publish candidates: row's 16 candidates live across its 4 q-lanes ----
    {
        const int r0 = 16 * w + rl;
        float* cd0 = s_cd + r0 * 16 + q * 4;
        int*   ci0 = s_ci + r0 * 16 + q * 4;
        cd0[0] = tA.d0; cd0[1] = tA.d1; cd0[2] = tA.d2; cd0[3] = tA.d3;
        ci0[0] = tA.i0; ci0[1] = tA.i1; ci0[2] = tA.i2; ci0[3] = tA.i3;
        float* cd1 = s_cd + (r0 + 8) * 16 + q * 4;
        int*   ci1 = s_ci + (r0 + 8) * 16 + q * 4;
        cd1[0] = tB.d0; cd1[1] = tB.d1; cd1[2] = tB.d2; cd1[3] = tB.d3;
        ci1[0] = tB.i0; ci1[1] = tB.i1; ci1[2] = tB.i2; ci1[3] = tB.i3;
    }
    __syncthreads();

    // ---- merge 16 -> 4 per sample (lexicographic (dist, idx)) ----
    if (tid < MTILE) {
        float cd[16]; int ci[16];
#pragma unroll
        for (int j = 0; j < 16; j++) { cd[j] = s_cd[tid * 16 + j]; ci[j] = s_ci[tid * 16 + j]; }
#pragma unroll
        for (int k = 0; k < KNN; k++) {
            int best = 0;
#pragma unroll
            for (int j = 1; j < 16; j++)
                if (cd[j] < cd[best] || (cd[j] == cd[best] && ci[j] < ci[best])) best = j;
            s_idx[tid * 4 + k] = ci[best];
            cd[best] = 3.4e38f;
        }
    }
    __syncthreads();

    // ---- phase B: warp-cooperative apply, 16 samples per warp ----
    const int prow = lane >> 3;
    const int e4   = lane & 7;
    const float4* offs4 = (const float4*)offs;

    for (int sbm = w; sbm < MTILE; sbm += 8) {
        float4 acc = make_float4(0.f, 0.f, 0.f, 0.f);
#pragma unroll
        for (int k = 0; k < KNN; k++) {
            int f = s_idx[sbm * 4 + k];
            const float4* w4 = (const float4*)(wts + (size_t)f * D * D);
            const float*  cf = ctrs + (size_t)f * D;
#pragma unroll
            for (int dd = 0; dd < 8; dd++) {
                int d = dd * 4 + prow;
                float4 wv = __ldg(w4 + d * 8 + e4);
                float  xc = s_x[sbm * 33 + d] - __ldg(cf + d);
                acc.x = fmaf(xc, wv.x, acc.x);
                acc.y = fmaf(xc, wv.y, acc.y);
                acc.z = fmaf(xc, wv.z, acc.z);
                acc.w = fmaf(xc, wv.w, acc.w);
            }
        }
#pragma unroll
        for (int off = 8; off < 32; off <<= 1) {
            acc.x += __shfl_xor_sync(0xffffffffu, acc.x, off);
            acc.y += __shfl_xor_sync(0xffffffffu, acc.y, off);
            acc.z += __shfl_xor_sync(0xffffffffu, acc.z, off);
            acc.w += __shfl_xor_sync(0xffffffffu, acc.w, off);
        }
        if (prow == 0) {
#pragma unroll
            for (int k = 0; k < KNN; k++) {
                int f = s_idx[sbm * 4 + k];
                float4 ov = __ldg(offs4 + f * 8 + e4);
                acc.x += ov.x; acc.y += ov.y; acc.z += ov.z; acc.w += ov.w;
            }
            ((float4*)(y + (size_t)(m0 + sbm) * D))[e4] = acc;
        }
    }
}

// ---------------- launch ----------------
extern "C" void kernel_launch(void* const* d_in, const int* in_sizes, int n_in,
                              void* d_out, int out_size)
{
    const float* x    = (const float*)d_in[0];
    const float* ctrs = (const float*)d_in[1];
    const float* wts  = (const float*)d_in[2];
    const float* offs = (const float*)d_in[3];
    float* y = (float*)d_out;

    int n_smps = in_sizes[0] / D;
    int n_fcns = in_sizes[1] / D;

    cudaFuncSetAttribute(pwl_gemm_kernel,
                         cudaFuncAttributeMaxDynamicSharedMemorySize, DYN_SMEM);

    prep_a_kernel<<<(n_smps * D + 255) / 256, 256>>>(x, n_smps * D);
    prep_b_kernel<<<(n_fcns + 255) / 256, 256>>>(ctrs, n_fcns);
    pwl_gemm_kernel<<<n_smps / MTILE, 256, DYN_SMEM>>>(x, ctrs, wts, offs, y, n_fcns);
}

// round 8
// speedup vs baseline: 1.0583x; 1.0583x over previous
#include <cuda_runtime.h>
#include <cuda_bf16.h>

typedef unsigned int       u32;
typedef unsigned long long u64;

#define D       32
#define KNN     4
#define KAUG    192        // 6 blocks of 32 (3-way bf16 split cross terms)
#define MTILE   128        // samples per CTA
#define NTILE   128        // centers per staged tile
#define KSTEPS  12         // 192 / 16
#define SWR     100        // smem row stride in 32-bit words (200 bf16, conflict-free)
#define ROWB    400        // smem row stride in bytes

// ---------------- smem layout (bytes) ----------------
#define OFF_A    0
#define SZ_AB    (MTILE * ROWB)            // 51200
#define OFF_B    (OFF_A + SZ_AB)           // two buffers
#define OFF_CN   (OFF_B + 2 * SZ_AB)       // 153600: 2048 floats
#define OFF_X    (OFF_CN + 8192)           // 161792: 128*33 floats
#define OFF_CD   (OFF_X + 16896)           // 178688: 128*16 floats
#define OFF_CI   (OFF_CD + 8192)           // 186880: 128*16 ints
#define OFF_IDX  (OFF_CI + 8192)           // 195072: 128*4 ints
#define DYN_SMEM (OFF_IDX + 2048)          // 197120

// ---------------- device scratch ----------------
__device__ __nv_bfloat16 g_a_aug[16384ull * KAUG];
__device__ __nv_bfloat16 g_b_aug[2048ull * KAUG];
__device__ float g_cn[2048];

// ---------------- helpers ----------------
__device__ __forceinline__ u32 smem_u32(const void* p) {
    u32 a;
    asm("{ .reg .u64 t; cvta.to.shared.u64 t, %1; cvt.u32.u64 %0, t; }" : "=r"(a) : "l"(p));
    return a;
}
#define CP16(dst, src) asm volatile("cp.async.cg.shared.global [%0], [%1], 16;" :: "r"(dst), "l"(src))
#define CP4(dst, src)  asm volatile("cp.async.ca.shared.global [%0], [%1], 4;"  :: "r"(dst), "l"(src))
#define CP_COMMIT()    asm volatile("cp.async.commit_group;")
#define CP_WAIT1()     asm volatile("cp.async.wait_group 1;" ::: "memory")
#define CP_WAIT0()     asm volatile("cp.async.wait_group 0;" ::: "memory")

__device__ __forceinline__ void mma4(float* d, const u32* a, u32 b0, u32 b1) {
    asm("mma.sync.aligned.m16n8k16.row.col.f32.bf16.bf16.f32 "
        "{%0,%1,%2,%3}, {%4,%5,%6,%7}, {%8,%9}, {%0,%1,%2,%3};"
        : "+f"(d[0]), "+f"(d[1]), "+f"(d[2]), "+f"(d[3])
        : "r"(a[0]), "r"(a[1]), "r"(a[2]), "r"(a[3]), "r"(b0), "r"(b1));
}

// stable top-4 (strict <, ties keep earlier index; inserts are in increasing f)
struct Top4 {
    float d0, d1, d2, d3;
    int   i0, i1, i2, i3;
    __device__ __forceinline__ void init() {
        d0 = d1 = d2 = d3 = 3.4e38f; i0 = i1 = i2 = i3 = 0;
    }
    __device__ __forceinline__ void insert(float sc, int f) {
        if (sc < d3) {
            bool g0 = sc < d0, g1 = sc < d1, g2 = sc < d2;
            float n3 = g2 ? d2 : sc;             int j3 = g2 ? i2 : f;
            float n2 = g2 ? (g1 ? d1 : sc) : d2; int j2 = g2 ? (g1 ? i1 : f) : i2;
            float n1 = g1 ? (g0 ? d0 : sc) : d1; int j1 = g1 ? (g0 ? i0 : f) : i1;
            d0 = g0 ? sc : d0;                   i0 = g0 ? f : i0;
            d1 = n1; i1 = j1; d2 = n2; i2 = j2; d3 = n3; i3 = j3;
        }
    }
};

// ---------------- prep: 3-way bf16 splits + cnorm ----------------
// A blocks: [u0,u1,u0,u1,u0,u2]; B blocks: [c0,c0,c1,c1,c2,c0]
// sum of products = u0c0+u1c0+u0c1+u1c1+u0c2+u2c0 ~= u.c (err ~2^-27 |u||c|)
__global__ void prep_a_kernel(const float* __restrict__ x, int n) {
    int i = blockIdx.x * blockDim.x + threadIdx.x;
    if (i >= n) return;
    int row = i >> 5, d = i & 31;
    float u = -2.0f * x[i];
    __nv_bfloat16 u0 = __float2bfloat16(u);
    float r1 = u - __bfloat162float(u0);
    __nv_bfloat16 u1 = __float2bfloat16(r1);
    float r2 = r1 - __bfloat162float(u1);
    __nv_bfloat16 u2 = __float2bfloat16(r2);
    __nv_bfloat16* a = g_a_aug + (size_t)row * KAUG;
    a[d] = u0; a[32 + d] = u1; a[64 + d] = u0;
    a[96 + d] = u1; a[128 + d] = u0; a[160 + d] = u2;
}

__global__ void prep_b_kernel(const float* __restrict__ ctrs, int n_fcns) {
    int f = blockIdx.x * blockDim.x + threadIdx.x;
    if (f >= n_fcns) return;
    float cn = 0.0f;
    __nv_bfloat16* b = g_b_aug + (size_t)f * KAUG;
    for (int d = 0; d < D; d++) {
        float c = ctrs[(size_t)f * D + d];
        cn += c * c;
        __nv_bfloat16 c0 = __float2bfloat16(c);
        float r1 = c - __bfloat162float(c0);
        __nv_bfloat16 c1 = __float2bfloat16(r1);
        float r2 = r1 - __bfloat162float(c1);
        __nv_bfloat16 c2 = __float2bfloat16(r2);
        b[d] = c0; b[32 + d] = c0; b[64 + d] = c1;
        b[96 + d] = c1; b[128 + d] = c2; b[160 + d] = c0;
    }
    g_cn[f] = cn;
}

// ---------------- main fused kernel ----------------
// 1 CTA = 128 samples x all centers, 256 threads (8 warps).
// Warp w owns M-rows [16w, 16w+16). A fragments (16x192) live in 48 regs.
// B streams via cp.async double-buffered 128-center tiles. Inner loop runs
// TWO 8-col blocks x TWO K-halves = 4 independent MMA chains (length 6) for
// latency hiding, then a fused fp32 top-4 epilogue. Then phase B.
__global__ __launch_bounds__(256, 1)
void pwl_gemm_kernel(const float* __restrict__ x,
                     const float* __restrict__ ctrs,
                     const float* __restrict__ wts,
                     const float* __restrict__ offs,
                     float* __restrict__ y,
                     int n_fcns)
{
    extern __shared__ __align__(16) char smem[];
    const int tid  = threadIdx.x;
    const int lane = tid & 31;
    const int w    = tid >> 5;
    const int q    = lane & 3;        // k-quad within fragment
    const int rl   = lane >> 2;       // row/col-lane within fragment
    const int m0   = blockIdx.x * MTILE;
    const int NT   = n_fcns / NTILE;  // 16

    const u32 sb   = smem_u32(smem);
    float* s_cn  = (float*)(smem + OFF_CN);
    float* s_x   = (float*)(smem + OFF_X);    // [128][33]
    float* s_cd  = (float*)(smem + OFF_CD);   // [128][16]
    int*   s_ci  = (int*)  (smem + OFF_CI);   // [128][16]
    int*   s_idx = (int*)  (smem + OFF_IDX);  // [128][4]

    // stage a 128-row x 192-col bf16 tile into padded smem (row stride 400B)
    auto stage_tile = [&](const __nv_bfloat16* g, int row0, u32 dst) {
#pragma unroll
        for (int kk = 0; kk < 12; kk++) {
            int e = tid + kk * 256;          // 0..3071 16B-chunks
            int r = e / 24, c = e % 24;
            CP16(dst + (u32)(r * ROWB + c * 16),
                 (const char*)(g + (size_t)(row0 + r) * KAUG) + c * 16);
        }
    };

    // group 0: A tile + cnorms + B tile 0 ; group 1: B tile 1
    stage_tile(g_a_aug, m0, sb + OFF_A);
#pragma unroll
    for (int i = 0; i < 8; i++)
        CP4(sb + OFF_CN + (tid + i * 256) * 4, (const char*)(g_cn + tid + i * 256));
    stage_tile(g_b_aug, 0, sb + OFF_B);
    CP_COMMIT();
    stage_tile(g_b_aug, NTILE, sb + OFF_B + SZ_AB);
    CP_COMMIT();

    // stage raw x for phase B (plain LDG->STS, overlaps with cp.async)
    for (int i = tid; i < MTILE * D; i += 256) {
        int r = i >> 5, d = i & 31;
        s_x[r * 33 + d] = __ldg(x + (size_t)(m0 + r) * D + d);
    }

    CP_WAIT1();              // group 0 (A + cn + B0) resident
    __syncthreads();

    // ---- load this warp's A fragments into registers (once) ----
    u32 af[KSTEPS][4];
    {
        const u32* aw = (const u32*)(smem + OFF_A);
        const int r0 = 16 * w + rl;
#pragma unroll
        for (int s = 0; s < KSTEPS; s++) {
            int base = r0 * SWR + s * 8 + q;
            af[s][0] = aw[base];
            af[s][1] = aw[base + 8 * SWR];
            af[s][2] = aw[base + 4];
            af[s][3] = aw[base + 8 * SWR + 4];
        }
    }

    Top4 tA, tB;             // rows r0 and r0+8
    tA.init(); tB.init();

    for (int t = 0; t < NT; t++) {
        if (t > 0) { if (t == NT - 1) CP_WAIT0(); else CP_WAIT1(); __syncthreads(); }

        const u32* bw = (const u32*)(smem + OFF_B + (t & 1) * SZ_AB);
        const float* cnb = s_cn + t * NTILE;

#pragma unroll 2
        for (int j = 0; j < 16; j += 2) {
            // two 8-col blocks x two K-halves: 4 independent MMA chains
            const u32* bj0 = bw + (j * 8 + rl) * SWR + q;
            const u32* bj1 = bj0 + 8 * SWR;
            float e0[4] = {0.f, 0.f, 0.f, 0.f};   // block j,   K 0..95
            float e1[4] = {0.f, 0.f, 0.f, 0.f};   // block j,   K 96..191
            float f0[4] = {0.f, 0.f, 0.f, 0.f};   // block j+1, K 0..95
            float f1[4] = {0.f, 0.f, 0.f, 0.f};   // block j+1, K 96..191
#pragma unroll
            for (int s = 0; s < 6; s++) {
                mma4(e0, af[s],     bj0[s * 8],       bj0[s * 8 + 4]);
                mma4(e1, af[s + 6], bj0[(s + 6) * 8], bj0[(s + 6) * 8 + 4]);
                mma4(f0, af[s],     bj1[s * 8],       bj1[s * 8 + 4]);
                mma4(f1, af[s + 6], bj1[(s + 6) * 8], bj1[(s + 6) * 8 + 4]);
            }
            const int g0 = t * NTILE + j * 8 + q * 2;
            float2 cnx = *(const float2*)(cnb + j * 8 + q * 2);
            float2 cny = *(const float2*)(cnb + j * 8 + 8 + q * 2);
            tA.insert(e0[0] + e1[0] + cnx.x, g0);
            tA.insert(e0[1] + e1[1] + cnx.y, g0 + 1);
            tB.insert(e0[2] + e1[2] + cnx.x, g0);
            tB.insert(e0[3] + e1[3] + cnx.y, g0 + 1);
            tA.insert(f0[0] + f1[0] + cny.x, g0 + 8);
            tA.insert(f0[1] + f1[1] + cny.y, g0 + 9);
            tB.insert(f0[2] + f1[2] + cny.x, g0 + 8);
            tB.insert(f0[3] + f1[3] + cny.y, g0 + 9);
        }

        __syncthreads();     // all warps done reading this B buffer
        if (t + 2 < NT) {
            stage_tile(g_b_aug, (t + 2) * NTILE, sb + OFF_B + (t & 1) * SZ_AB);
            CP_COMMIT();
        }
    }

    // ---- publish candidates: row's 16 candidates live across its 4 q-lanes ----
    {
        const int r0 = 16 * w + rl;
        float* cd0 = s_cd + r0 * 16 + q * 4;
        int*   ci0 = s_ci + r0 * 16 + q * 4;
        cd0[0] = tA.d0; cd0[1] = tA.d1; cd0[2] = tA.d2; cd0[3] = tA.d3;
        ci0[0] = tA.i0; ci0[1] = tA.i1; ci0[2] = tA.i2; ci0[3] = tA.i3;
        float* cd1 = s_cd + (r0 + 8) * 16 + q * 4;
        int*   ci1 = s_ci + (r0 + 8) * 16 + q * 4;
        cd1[0] = tB.d0; cd1[1] = tB.d1; cd1[2] = tB.d2; cd1[3] = tB.d3;
        ci1[0] = tB.i0; ci1[1] = tB.i1; ci1[2] = tB.i2; ci1[3] = tB.i3;
    }
    __syncthreads();

    // ---- merge 16 -> 4 per sample (lexicographic (dist, idx)) ----
    if (tid < MTILE) {
        float cd[16]; int ci[16];
#pragma unroll
        for (int j = 0; j < 16; j++) { cd[j] = s_cd[tid * 16 + j]; ci[j] = s_ci[tid * 16 + j]; }
#pragma unroll
        for (int k = 0; k < KNN; k++) {
            int best = 0;
#pragma unroll
            for (int j = 1; j < 16; j++)
                if (cd[j] < cd[best] || (cd[j] == cd[best] && ci[j] < ci[best])) best = j;
            s_idx[tid * 4 + k] = ci[best];
            cd[best] = 3.4e38f;
        }
    }
    __syncthreads();

    // ---- phase B: warp-cooperative apply, 16 samples per warp ----
    const int prow = lane >> 3;
    const int e4   = lane & 7;
    const float4* offs4 = (const float4*)offs;

    for (int sbm = w; sbm < MTILE; sbm += 8) {
        float4 acc = make_float4(0.f, 0.f, 0.f, 0.f);
#pragma unroll
        for (int k = 0; k < KNN; k++) {
            int f = s_idx[sbm * 4 + k];
            const float4* w4 = (const float4*)(wts + (size_t)f * D * D);
            const float*  cf = ctrs + (size_t)f * D;
#pragma unroll
            for (int dd = 0; dd < 8; dd++) {
                int d = dd * 4 + prow;
                float4 wv = __ldg(w4 + d * 8 + e4);
                float  xc = s_x[sbm * 33 + d] - __ldg(cf + d);
                acc.x = fmaf(xc, wv.x, acc.x);
                acc.y = fmaf(xc, wv.y, acc.y);
                acc.z = fmaf(xc, wv.z, acc.z);
                acc.w = fmaf(xc, wv.w, acc.w);
            }
        }
#pragma unroll
        for (int off = 8; off < 32; off <<= 1) {
            acc.x += __shfl_xor_sync(0xffffffffu, acc.x, off);
            acc.y += __shfl_xor_sync(0xffffffffu, acc.y, off);
            acc.z += __shfl_xor_sync(0xffffffffu, acc.z, off);
            acc.w += __shfl_xor_sync(0xffffffffu, acc.w, off);
        }
        if (prow == 0) {
#pragma unroll
            for (int k = 0; k < KNN; k++) {
                int f = s_idx[sbm * 4 + k];
                float4 ov = __ldg(offs4 + f * 8 + e4);
                acc.x += ov.x; acc.y += ov.y; acc.z += ov.z; acc.w += ov.w;
            }
            ((float4*)(y + (size_t)(m0 + sbm) * D))[e4] = acc;
        }
    }
}

// ---------------- launch ----------------
extern "C" void kernel_launch(void* const* d_in, const int* in_sizes, int n_in,
                              void* d_out, int out_size)
{
    const float* x    = (const float*)d_in[0];
    const float* ctrs = (const float*)d_in[1];
    const float* wts  = (const float*)d_in[2];
    const float* offs = (const float*)d_in[3];
    float* y = (float*)d_out;

    int n_smps = in_sizes[0] / D;
    int n_fcns = in_sizes[1] / D;

    cudaFuncSetAttribute(pwl_gemm_kernel,
                         cudaFuncAttributeMaxDynamicSharedMemorySize, DYN_SMEM);

    prep_a_kernel<<<(n_smps * D + 255) / 256, 256>>>(x, n_smps * D);
    prep_b_kernel<<<(n_fcns + 255) / 256, 256>>>(ctrs, n_fcns);
    pwl_gemm_kernel<<<n_smps / MTILE, 256, DYN_SMEM>>>(x, ctrs, wts, offs, y, n_fcns);
}

// round 9
// speedup vs baseline: 1.3078x; 1.2358x over previous
#include <cuda_runtime.h>

typedef unsigned long long u64;

#define D      32
#define KNN    4
#define WARPS  8
#define SPB    32
#define TILE   32
#define SHARD  256   // 2048 / WARPS, exactly 8 tiles of 32

// ---------------- packed f32x2 helpers (sm_103a FFMA2 path) ----------------
__device__ __forceinline__ u64 fma2(u64 a, u64 b, u64 c) {
    u64 r;
    asm("fma.rn.f32x2 %0, %1, %2, %3;" : "=l"(r) : "l"(a), "l"(b), "l"(c));
    return r;
}
__device__ __forceinline__ u64 add2(u64 a, u64 b) {
    u64 r;
    asm("add.rn.f32x2 %0, %1, %2;" : "=l"(r) : "l"(a), "l"(b));
    return r;
}
__device__ __forceinline__ void unpack2(u64 a, float& lo, float& hi) {
    asm("mov.b64 {%0, %1}, %2;" : "=f"(lo), "=f"(hi) : "l"(a));
}
__device__ __forceinline__ u64 pack2(float a, float b) {
    u64 r;
    asm("mov.b64 %0, {%1, %2};" : "=l"(r) : "f"(a), "f"(b));
    return r;
}

// ---------------- scratch: per-center squared norms ----------------
__device__ float g_cnorm[4096];

__global__ void cnorm_kernel(const float* __restrict__ ctrs, int n_fcns) {
    int f = blockIdx.x * blockDim.x + threadIdx.x;
    if (f < n_fcns) {
        const float4* c4 = (const float4*)(ctrs + (size_t)f * D);
        float s = 0.0f;
#pragma unroll
        for (int j = 0; j < D / 4; j++) {
            float4 q = __ldg(c4 + j);
            s += q.x * q.x + q.y * q.y + q.z * q.z + q.w * q.w;
        }
        g_cnorm[f] = s;
    }
}

// ---------------- main fused kernel ----------------
// Block = 256 threads = 8 warps, 32 samples (lane == sample).
// Phase A: warp w scans centers [w*256, (w+1)*256) in 8 exact tiles of 32,
//          keeping a per-lane stable top-4. 32 candidates/sample, merged
//          lexicographically (dist, idx). Phase B: 4 samples per warp.
__global__ __launch_bounds__(256, 4) void pwl_kernel(
    const float* __restrict__ x,
    const float* __restrict__ ctrs,
    const float* __restrict__ wts,
    const float* __restrict__ offs,
    float* __restrict__ y,
    int n_fcns)
{
    __shared__ __align__(16) float s_ctr[WARPS][TILE * D];   // 32 KB
    __shared__ float s_cn[WARPS][TILE];
    __shared__ float s_x[SPB][D + 1];
    __shared__ float s_cd[SPB][WARPS * KNN];
    __shared__ int   s_ci[SPB][WARPS * KNN];
    __shared__ int   s_idx[SPB][KNN];

    const int lane = threadIdx.x & 31;
    const int w    = threadIdx.x >> 5;
    const int srow = blockIdx.x * SPB + lane;

    // ---- load x row: registers hold packed (-2*x); warp 0 stores raw x ----
    u64 xp[16];
    {
        const float4* xg = (const float4*)(x + (size_t)srow * D);
#pragma unroll
        for (int j = 0; j < 8; j++) {
            float4 q = __ldg(xg + j);
            if (w == 0) {
                s_x[lane][4 * j + 0] = q.x;
                s_x[lane][4 * j + 1] = q.y;
                s_x[lane][4 * j + 2] = q.z;
                s_x[lane][4 * j + 3] = q.w;
            }
            xp[2 * j]     = pack2(-2.0f * q.x, -2.0f * q.y);
            xp[2 * j + 1] = pack2(-2.0f * q.z, -2.0f * q.w);
        }
    }

    const int fstart = w * SHARD;

    float bd0 = 3.4e38f, bd1 = 3.4e38f, bd2 = 3.4e38f, bd3 = 3.4e38f;
    int   bi0 = 0, bi1 = 0, bi2 = 0, bi3 = 0;

    const float4* cg4 = (const float4*)ctrs;

    for (int t = fstart; t < fstart + SHARD; t += TILE) {
        __syncwarp();
        // stage TILE centers for this warp (exact, no clamps)
#pragma unroll
        for (int i = 0; i < TILE * D / 4 / 32; i++) {          // 8 iters
            int e = i * 32 + lane;                             // 0..255
            ((float4*)s_ctr[w])[e] = __ldg(cg4 + (size_t)(t + (e >> 3)) * 8 + (e & 7));
        }
        s_cn[w][lane] = g_cnorm[t + lane];                     // TILE==32
        __syncwarp();

#pragma unroll 2
        for (int ff = 0; ff < TILE; ff++) {
            const ulonglong2* c2 = (const ulonglong2*)(s_ctr[w] + ff * D);
            u64 a0 = 0ull, a1 = 0ull, a2 = 0ull;
            u64 a3 = (u64)__float_as_uint(s_cn[w][ff]);   // seed (cnorm, 0)
#pragma unroll
            for (int j = 0; j < 4; j++) {
                ulonglong2 qa = c2[2 * j];
                ulonglong2 qb = c2[2 * j + 1];
                a0 = fma2(xp[4 * j + 0], qa.x, a0);
                a1 = fma2(xp[4 * j + 1], qa.y, a1);
                a2 = fma2(xp[4 * j + 2], qb.x, a2);
                a3 = fma2(xp[4 * j + 3], qb.y, a3);
            }
            u64 r = add2(add2(a0, a1), add2(a2, a3));
            float lo, hi;
            unpack2(r, lo, hi);
            float sc = lo + hi;                 // == cnorm - 2*dot (rank-equiv)
            int f = t + ff;
            // single-branch, SEL-body stable insertion (strict <)
            if (sc < bd3) {
                bool g0 = sc < bd0, g1 = sc < bd1, g2 = sc < bd2;
                float nb3 = g2 ? bd2 : sc;              int ni3 = g2 ? bi2 : f;
                float nb2 = g2 ? (g1 ? bd1 : sc) : bd2; int ni2 = g2 ? (g1 ? bi1 : f) : bi2;
                float nb1 = g1 ? (g0 ? bd0 : sc) : bd1; int ni1 = g1 ? (g0 ? bi0 : f) : bi1;
                bd0 = g0 ? sc : bd0;                    bi0 = g0 ? f : bi0;
                bd1 = nb1; bi1 = ni1;
                bd2 = nb2; bi2 = ni2;
                bd3 = nb3; bi3 = ni3;
            }
        }
    }

    // ---- publish candidates, merge 32 -> 4 per sample ----
    s_cd[lane][w * KNN + 0] = bd0;  s_ci[lane][w * KNN + 0] = bi0;
    s_cd[lane][w * KNN + 1] = bd1;  s_ci[lane][w * KNN + 1] = bi1;
    s_cd[lane][w * KNN + 2] = bd2;  s_ci[lane][w * KNN + 2] = bi2;
    s_cd[lane][w * KNN + 3] = bd3;  s_ci[lane][w * KNN + 3] = bi3;
    __syncthreads();

    if (threadIdx.x < SPB) {
        const int ms = threadIdx.x;
        float cd[WARPS * KNN];
        int   ci[WARPS * KNN];
#pragma unroll
        for (int j = 0; j < WARPS * KNN; j++) {
            cd[j] = s_cd[ms][j];
            ci[j] = s_ci[ms][j];
        }
#pragma unroll
        for (int tt = 0; tt < KNN; tt++) {
            int best = 0;
#pragma unroll
            for (int j = 1; j < WARPS * KNN; j++) {
                // lexicographic (dist, idx): matches top_k tie-break
                if (cd[j] < cd[best] || (cd[j] == cd[best] && ci[j] < ci[best]))
                    best = j;
            }
            s_idx[ms][tt] = ci[best];
            cd[best] = 3.4e38f;
        }
    }
    __syncthreads();

    // ---- phase B: warp-cooperative apply, 4 samples per warp ----
    // lane = (row = lane>>3 in 0..3, e4 = lane&7): covers d in {row, row+4, ...}
    // and output columns [4*e4, 4*e4+4).
    const int row = lane >> 3;
    const int e4  = lane & 7;
    const float4* offs4 = (const float4*)offs;

    for (int sb = w; sb < SPB; sb += WARPS) {
        float4 acc = make_float4(0.f, 0.f, 0.f, 0.f);
#pragma unroll
        for (int t = 0; t < KNN; t++) {
            int f = s_idx[sb][t];
            const float4* w4 = (const float4*)(wts + (size_t)f * D * D);
            const float*  cf = ctrs + (size_t)f * D;
#pragma unroll
            for (int dd = 0; dd < 8; dd++) {
                int d = dd * 4 + row;
                float4 wv = __ldg(w4 + d * 8 + e4);
                float  xc = s_x[sb][d] - __ldg(cf + d);
                acc.x = fmaf(xc, wv.x, acc.x);
                acc.y = fmaf(xc, wv.y, acc.y);
                acc.z = fmaf(xc, wv.z, acc.z);
                acc.w = fmaf(xc, wv.w, acc.w);
            }
        }
#pragma unroll
        for (int off = 8; off < 32; off <<= 1) {
            acc.x += __shfl_xor_sync(0xffffffffu, acc.x, off);
            acc.y += __shfl_xor_sync(0xffffffffu, acc.y, off);
            acc.z += __shfl_xor_sync(0xffffffffu, acc.z, off);
            acc.w += __shfl_xor_sync(0xffffffffu, acc.w, off);
        }
        if (row == 0) {
#pragma unroll
            for (int t = 0; t < KNN; t++) {
                int f = s_idx[sb][t];
                float4 ov = __ldg(offs4 + f * 8 + e4);
                acc.x += ov.x; acc.y += ov.y; acc.z += ov.z; acc.w += ov.w;
            }
            ((float4*)(y + (size_t)(blockIdx.x * SPB + sb) * D))[e4] = acc;
        }
    }
}

// ---------------- launch ----------------
extern "C" void kernel_launch(void* const* d_in, const int* in_sizes, int n_in,
                              void* d_out, int out_size)
{
    const float* x    = (const float*)d_in[0];
    const float* ctrs = (const float*)d_in[1];
    const float* wts  = (const float*)d_in[2];
    const float* offs = (const float*)d_in[3];
    float* y = (float*)d_out;

    int n_smps = in_sizes[0] / D;
    int n_fcns = in_sizes[1] / D;

    cnorm_kernel<<<(n_fcns + 255) / 256, 256>>>(ctrs, n_fcns);
    pwl_kernel<<<n_smps / SPB, 256>>>(x, ctrs, wts, offs, y, n_fcns);
}

// round 10
// speedup vs baseline: 1.7109x; 1.3082x over previous
#include <cuda_runtime.h>

typedef unsigned long long u64;

#define D      32
#define KNN    4
#define WARPS  6
#define SPB    64        // samples per block; lane owns (lane, lane+32)
#define TILE   32
#define NTILES 64        // 2048 / 32

// ---------------- packed f32x2 helpers (sm_103a FFMA2 path) ----------------
__device__ __forceinline__ u64 fma2(u64 a, u64 b, u64 c) {
    u64 r;
    asm("fma.rn.f32x2 %0, %1, %2, %3;" : "=l"(r) : "l"(a), "l"(b), "l"(c));
    return r;
}
__device__ __forceinline__ u64 add2(u64 a, u64 b) {
    u64 r;
    asm("add.rn.f32x2 %0, %1, %2;" : "=l"(r) : "l"(a), "l"(b));
    return r;
}
__device__ __forceinline__ void unpack2(u64 a, float& lo, float& hi) {
    asm("mov.b64 {%0, %1}, %2;" : "=f"(lo), "=f"(hi) : "l"(a));
}
__device__ __forceinline__ u64 pack2(float a, float b) {
    u64 r;
    asm("mov.b64 %0, {%1, %2};" : "=l"(r) : "f"(a), "f"(b));
    return r;
}

// ---------------- scratch: per-center squared norms ----------------
__device__ float g_cnorm[4096];

__global__ void cnorm_kernel(const float* __restrict__ ctrs, int n_fcns) {
    int f = blockIdx.x * blockDim.x + threadIdx.x;
    if (f < n_fcns) {
        const float4* c4 = (const float4*)(ctrs + (size_t)f * D);
        float s = 0.0f;
#pragma unroll
        for (int j = 0; j < D / 4; j++) {
            float4 q = __ldg(c4 + j);
            s += q.x * q.x + q.y * q.y + q.z * q.z + q.w * q.w;
        }
        g_cnorm[f] = s;
    }
}

// select-only stable top-4 insert; SAFE when sc >= d3 (no-op). Strict <.
#define INS4(sc, f, d0, d1, d2, d3, i0, i1, i2, i3) do {                      \
    bool h0 = (sc) < d0, h1 = (sc) < d1, h2 = (sc) < d2, h3 = (sc) < d3;      \
    float n3 = h3 ? (h2 ? d2 : (sc)) : d3;  int m3 = h3 ? (h2 ? i2 : (f)) : i3; \
    float n2 = h2 ? (h1 ? d1 : (sc)) : d2;  int m2 = h2 ? (h1 ? i1 : (f)) : i2; \
    float n1 = h1 ? (h0 ? d0 : (sc)) : d1;  int m1 = h1 ? (h0 ? i0 : (f)) : i1; \
    d0 = h0 ? (sc) : d0;                    i0 = h0 ? (f) : i0;               \
    d1 = n1; i1 = m1; d2 = n2; i2 = m2; d3 = n3; i3 = m3;                     \
} while (0)

// ---------------- main fused kernel ----------------
// Block = 192 threads = 6 warps, 64 samples. Lane owns samples lane & lane+32,
// so every center broadcast (8x LDS.128 + cnorm) serves 64 sample-pairs.
// Phase A: warp w scans a tile-granular shard (11/11/11/11/10/10 tiles of 32),
// keeping two per-lane stable top-4s. Merge 24 -> 4 per sample. Phase B apply.
__global__ __launch_bounds__(192, 2) void pwl_kernel(
    const float* __restrict__ x,
    const float* __restrict__ ctrs,
    const float* __restrict__ wts,
    const float* __restrict__ offs,
    float* __restrict__ y,
    int n_fcns)
{
    __shared__ __align__(16) float s_ctr[WARPS][TILE * D];   // 24 KB
    __shared__ float s_cn[WARPS][TILE];
    __shared__ float s_x[SPB * (D + 1)];
    __shared__ float s_cd[SPB][WARPS * KNN];
    __shared__ int   s_ci[SPB][WARPS * KNN];
    __shared__ int   s_idx[SPB][KNN];

    const int lane = threadIdx.x & 31;
    const int w    = threadIdx.x >> 5;
    const int rowA = blockIdx.x * SPB + lane;
    const int rowB = rowA + 32;

    // ---- load both sample rows: registers hold packed (-2*x); warp 0 -> smem ----
    u64 xpA[16], xpB[16];
    {
        const float4* ga = (const float4*)(x + (size_t)rowA * D);
        const float4* gb = (const float4*)(x + (size_t)rowB * D);
#pragma unroll
        for (int j = 0; j < 8; j++) {
            float4 qa = __ldg(ga + j);
            float4 qb = __ldg(gb + j);
            if (w == 0) {
                float* da = s_x + lane * (D + 1) + 4 * j;
                float* db = s_x + (lane + 32) * (D + 1) + 4 * j;
                da[0] = qa.x; da[1] = qa.y; da[2] = qa.z; da[3] = qa.w;
                db[0] = qb.x; db[1] = qb.y; db[2] = qb.z; db[3] = qb.w;
            }
            xpA[2 * j]     = pack2(-2.0f * qa.x, -2.0f * qa.y);
            xpA[2 * j + 1] = pack2(-2.0f * qa.z, -2.0f * qa.w);
            xpB[2 * j]     = pack2(-2.0f * qb.x, -2.0f * qb.y);
            xpB[2 * j + 1] = pack2(-2.0f * qb.z, -2.0f * qb.w);
        }
    }

    // ---- tile-granular shard: warps 0-3 get 11 tiles, warps 4-5 get 10 ----
    const int tb = (w < 4) ? w * 11 : 44 + (w - 4) * 10;
    const int te = tb + ((w < 4) ? 11 : 10);

    float A0 = 3.4e38f, A1 = 3.4e38f, A2 = 3.4e38f, A3 = 3.4e38f;
    float B0 = 3.4e38f, B1 = 3.4e38f, B2 = 3.4e38f, B3 = 3.4e38f;
    int   Ai0 = 0, Ai1 = 0, Ai2 = 0, Ai3 = 0;
    int   Bi0 = 0, Bi1 = 0, Bi2 = 0, Bi3 = 0;

    const float4* cg4 = (const float4*)ctrs;

    for (int tt = tb; tt < te; tt++) {
        const int t = tt * TILE;
        __syncwarp();
        // stage 32 centers for this warp (exact tiles, no guards)
#pragma unroll
        for (int i = 0; i < 8; i++) {
            int e = i * 32 + lane;                             // 0..255
            ((float4*)s_ctr[w])[e] = __ldg(cg4 + (size_t)(t + (e >> 3)) * 8 + (e & 7));
        }
        s_cn[w][lane] = g_cnorm[t + lane];
        __syncwarp();

#pragma unroll 2
        for (int ff = 0; ff < TILE; ff++) {
            const ulonglong2* c2 = (const ulonglong2*)(s_ctr[w] + ff * D);
            u64 cnp = (u64)__float_as_uint(s_cn[w][ff]);       // (cnorm, 0)
            u64 a0 = 0ull, a1 = 0ull, a2 = 0ull, a3 = cnp;
            u64 b0 = 0ull, b1 = 0ull, b2 = 0ull, b3 = cnp;
#pragma unroll
            for (int j = 0; j < 4; j++) {
                ulonglong2 qa = c2[2 * j];
                ulonglong2 qb = c2[2 * j + 1];
                a0 = fma2(xpA[4 * j + 0], qa.x, a0);
                b0 = fma2(xpB[4 * j + 0], qa.x, b0);
                a1 = fma2(xpA[4 * j + 1], qa.y, a1);
                b1 = fma2(xpB[4 * j + 1], qa.y, b1);
                a2 = fma2(xpA[4 * j + 2], qb.x, a2);
                b2 = fma2(xpB[4 * j + 2], qb.x, b2);
                a3 = fma2(xpA[4 * j + 3], qb.y, a3);
                b3 = fma2(xpB[4 * j + 3], qb.y, b3);
            }
            u64 ra = add2(add2(a0, a1), add2(a2, a3));
            u64 rb = add2(add2(b0, b1), add2(b2, b3));
            float la, ha, lb, hb;
            unpack2(ra, la, ha);
            unpack2(rb, lb, hb);
            float scA = la + ha;               // == cnorm - 2*dot (rank-equiv)
            float scB = lb + hb;
            const int f = t + ff;
            if (scA < A3 || scB < B3) {        // rare after warmup
                INS4(scA, f, A0, A1, A2, A3, Ai0, Ai1, Ai2, Ai3);
                INS4(scB, f, B0, B1, B2, B3, Bi0, Bi1, Bi2, Bi3);
            }
        }
    }

    // ---- publish candidates, merge 24 -> 4 per sample ----
    s_cd[lane][w * KNN + 0] = A0;       s_ci[lane][w * KNN + 0] = Ai0;
    s_cd[lane][w * KNN + 1] = A1;       s_ci[lane][w * KNN + 1] = Ai1;
    s_cd[lane][w * KNN + 2] = A2;       s_ci[lane][w * KNN + 2] = Ai2;
    s_cd[lane][w * KNN + 3] = A3;       s_ci[lane][w * KNN + 3] = Ai3;
    s_cd[lane + 32][w * KNN + 0] = B0;  s_ci[lane + 32][w * KNN + 0] = Bi0;
    s_cd[lane + 32][w * KNN + 1] = B1;  s_ci[lane + 32][w * KNN + 1] = Bi1;
    s_cd[lane + 32][w * KNN + 2] = B2;  s_ci[lane + 32][w * KNN + 2] = Bi2;
    s_cd[lane + 32][w * KNN + 3] = B3;  s_ci[lane + 32][w * KNN + 3] = Bi3;
    __syncthreads();

    if (threadIdx.x < SPB) {
        const int ms = threadIdx.x;
        float cd[WARPS * KNN];
        int   ci[WARPS * KNN];
#pragma unroll
        for (int j = 0; j < WARPS * KNN; j++) {
            cd[j] = s_cd[ms][j];
            ci[j] = s_ci[ms][j];
        }
#pragma unroll
        for (int k = 0; k < KNN; k++) {
            int best = 0;
#pragma unroll
            for (int j = 1; j < WARPS * KNN; j++) {
                // lexicographic (dist, idx): matches top_k tie-break
                if (cd[j] < cd[best] || (cd[j] == cd[best] && ci[j] < ci[best]))
                    best = j;
            }
            s_idx[ms][k] = ci[best];
            cd[best] = 3.4e38f;
        }
    }
    __syncthreads();

    // ---- phase B: warp-cooperative apply ----
    // lane = (prow = lane>>3 in 0..3, e4 = lane&7): covers d in {prow, prow+4, ...}
    // and output columns [4*e4, 4*e4+4).
    const int prow = lane >> 3;
    const int e4   = lane & 7;
    const float4* offs4 = (const float4*)offs;

    for (int sb = w; sb < SPB; sb += WARPS) {
        float4 acc = make_float4(0.f, 0.f, 0.f, 0.f);
#pragma unroll
        for (int k = 0; k < KNN; k++) {
            int f = s_idx[sb][k];
            const float4* w4 = (const float4*)(wts + (size_t)f * D * D);
            const float*  cf = ctrs + (size_t)f * D;
#pragma unroll
            for (int dd = 0; dd < 8; dd++) {
                int d = dd * 4 + prow;
                float4 wv = __ldg(w4 + d * 8 + e4);
                float  xc = s_x[sb * (D + 1) + d] - __ldg(cf + d);
                acc.x = fmaf(xc, wv.x, acc.x);
                acc.y = fmaf(xc, wv.y, acc.y);
                acc.z = fmaf(xc, wv.z, acc.z);
                acc.w = fmaf(xc, wv.w, acc.w);
            }
        }
#pragma unroll
        for (int off = 8; off < 32; off <<= 1) {
            acc.x += __shfl_xor_sync(0xffffffffu, acc.x, off);
            acc.y += __shfl_xor_sync(0xffffffffu, acc.y, off);
            acc.z += __shfl_xor_sync(0xffffffffu, acc.z, off);
            acc.w += __shfl_xor_sync(0xffffffffu, acc.w, off);
        }
        if (prow == 0) {
#pragma unroll
            for (int k = 0; k < KNN; k++) {
                int f = s_idx[sb][k];
                float4 ov = __ldg(offs4 + f * 8 + e4);
                acc.x += ov.x; acc.y += ov.y; acc.z += ov.z; acc.w += ov.w;
            }
            ((float4*)(y + (size_t)(blockIdx.x * SPB + sb) * D))[e4] = acc;
        }
    }
}

// ---------------- launch ----------------
extern "C" void kernel_launch(void* const* d_in, const int* in_sizes, int n_in,
                              void* d_out, int out_size)
{
    const float* x    = (const float*)d_in[0];
    const float* ctrs = (const float*)d_in[1];
    const float* wts  = (const float*)d_in[2];
    const float* offs = (const float*)d_in[3];
    float* y = (float*)d_out;

    int n_smps = in_sizes[0] / D;
    int n_fcns = in_sizes[1] / D;

    cnorm_kernel<<<(n_fcns + 255) / 256, 256>>>(ctrs, n_fcns);
    pwl_kernel<<<n_smps / SPB, 192>>>(x, ctrs, wts, offs, y, n_fcns);
}